// round 17
// baseline (speedup 1.0000x reference)
#include <cuda_runtime.h>

typedef unsigned long long u64;
typedef ulonglong2 ull2;

// Fixed dims: B=8, N=256, NODE=128, EDGE=16, HID=256, MSG=128
#define MAXROWS 2048

__device__ u64   g_A[MAXROWS * 128];   // pairs over cols: A = h@W1a + b1
__device__ u64   g_Bv[MAXROWS * 128];  // pairs over cols: Bv = h@W1b
__device__ float g_S[MAXROWS * 256];   // per-row relu-sum
__device__ float g_deg[MAXROWS];
__device__ int   g_dummy;

__device__ __forceinline__ u64 fma2(u64 a, u64 b, u64 c) {
    u64 d; asm("fma.rn.f32x2 %0,%1,%2,%3;" : "=l"(d) : "l"(a), "l"(b), "l"(c)); return d;
}
__device__ __forceinline__ u64 add2(u64 a, u64 b) {
    u64 d; asm("add.rn.f32x2 %0,%1,%2;" : "=l"(d) : "l"(a), "l"(b)); return d;
}
__device__ __forceinline__ u64 pack2(float x, float y) {
    u64 d; asm("mov.b64 %0,{%1,%2};" : "=l"(d) : "f"(x), "f"(y)); return d;
}
__device__ __forceinline__ float2 unpack2(u64 v) {
    float2 f; asm("mov.b64 {%0,%1},%2;" : "=f"(f.x), "=f"(f.y) : "l"(v)); return f;
}
__device__ __forceinline__ u64 dup2(float x) { return pack2(x, x); }
__device__ __forceinline__ u64 max2z(u64 a) {
    float2 f = unpack2(a);
    return pack2(fmaxf(f.x, 0.f), fmaxf(f.y, 0.f));
}

// ---------------------------------------------------------------------------
// Align kernels FIRST: ncu capture slot is launch #4 -> mpnn_main.
// ---------------------------------------------------------------------------
__global__ void align_kernel()  { if (threadIdx.x == 0) g_dummy = 0; }
__global__ void align_kernel2() { if (threadIdx.x == 0) g_dummy = 1; }

// ---------------------------------------------------------------------------
// Precompute v5: grid = rows/8 = 256. Thread = one col-pair of [A|Bv],
// full K=128, 8 rows register-tiled as 4 row-pair packed accs.
// ---------------------------------------------------------------------------
__global__ __launch_bounds__(256) void precompute_kernel(
    const float* __restrict__ h, const float* __restrict__ W1,
    const float* __restrict__ b1)
{
    __shared__ __align__(16) u64 hd[128][4];

    const int r0 = blockIdx.x * 8;
    const int t  = threadIdx.x;

    if (t < 128) {
#pragma unroll
        for (int rp = 0; rp < 4; rp++) {
            float a = h[(size_t)(r0 + 2 * rp) * 128 + t];
            float b = h[(size_t)(r0 + 2 * rp + 1) * 128 + t];
            hd[t][rp] = pack2(a, b);
        }
    }
    __syncthreads();

    const int isB = t >> 7;
    const int cp  = t & 127;
    const u64* Wb = (const u64*)W1 + (size_t)(isB ? 128 * 128 : 0) + cp;

    u64 acc[4][2] = {{0ull,0ull},{0ull,0ull},{0ull,0ull},{0ull,0ull}};
#pragma unroll 1
    for (int kk = 0; kk < 128; kk += 8) {
        u64 wv[8];
#pragma unroll
        for (int i = 0; i < 8; i++)
            wv[i] = Wb[(size_t)(kk + i) * 128];
#pragma unroll
        for (int i = 0; i < 8; i++) {
            float2 wf = unpack2(wv[i]);
            u64 w0 = dup2(wf.x), w1 = dup2(wf.y);
            const int k = kk + i;
            ull2 h01 = *(const ull2*)&hd[k][0];
            ull2 h23 = *(const ull2*)&hd[k][2];
            acc[0][0] = fma2(h01.x, w0, acc[0][0]); acc[0][1] = fma2(h01.x, w1, acc[0][1]);
            acc[1][0] = fma2(h01.y, w0, acc[1][0]); acc[1][1] = fma2(h01.y, w1, acc[1][1]);
            acc[2][0] = fma2(h23.x, w0, acc[2][0]); acc[2][1] = fma2(h23.x, w1, acc[2][1]);
            acc[3][0] = fma2(h23.y, w0, acc[3][0]); acc[3][1] = fma2(h23.y, w1, acc[3][1]);
        }
    }
    u64* dst = isB ? g_Bv : g_A;
    const u64 bias = isB ? 0ull : ((const u64*)b1)[cp];
#pragma unroll
    for (int rp = 0; rp < 4; rp++) {
        float2 f0 = unpack2(acc[rp][0]);
        float2 f1 = unpack2(acc[rp][1]);
        dst[(size_t)(r0 + 2 * rp) * 128 + cp]     = add2(pack2(f0.x, f1.x), bias);
        dst[(size_t)(r0 + 2 * rp + 1) * 128 + cp] = add2(pack2(f0.y, f1.y), bias);
    }
}

// ---------------------------------------------------------------------------
// Main kernel: one (b,i) per block, thread = scalar h output, j-packed accs.
// L1-bandwidth fix: 4 lane-groups per warp walk the 8-j chunks in rotated
// order over a bank-padded eT (idx = (j>>5)*36 + (j&31)), so each LDS serves
// 4 distinct bank-disjoint addresses (64B/wavefront instead of 16B).
// ---------------------------------------------------------------------------
__global__ __launch_bounds__(256, 3) void mpnn_main(
    const float* __restrict__ adj, const float* __restrict__ ef,
    const float* __restrict__ W1)
{
    __shared__ __align__(16) float eTp[16][288];   // padded transposed edges (18 KB)
    __shared__ __align__(16) int   jlist[256];
    __shared__ __align__(16) float cav[256];
    __shared__ int   wcnt[8];
    __shared__ float wsum[8];
    __shared__ int   s_m;
    __shared__ float s_deg;

    const int row = blockIdx.x;
    const int bb  = row >> 8;
    const int t   = threadIdx.x;        // == output hidden index h
    const int w   = t >> 5, l = t & 31;

    const float av = adj[(size_t)row * 256 + t];
    const unsigned mask = __ballot_sync(0xffffffffu, av != 0.f);
    float ds = av;
#pragma unroll
    for (int off = 16; off; off >>= 1) ds += __shfl_xor_sync(0xffffffffu, ds, off);
    if (l == 0) { wcnt[w] = __popc(mask); wsum[w] = ds; }
    __syncthreads();
    if (t == 0) {
        int acc = 0; float d = 0.f;
#pragma unroll
        for (int i = 0; i < 8; i++) { int c = wcnt[i]; wcnt[i] = acc; acc += c; d += wsum[i]; }
        s_m = acc; s_deg = d;
    }

    u64 wd[16];
#pragma unroll
    for (int k = 0; k < 16; k++)
        wd[k] = dup2(W1[(size_t)(256 + k) * 256 + t]);
    const u64 a2 = dup2(((const float*)g_A)[(size_t)row * 256 + t]);
    const float* BvF = (const float*)g_Bv + ((size_t)(bb << 8)) * 256;

    __syncthreads();
    const int   m   = s_m;
    const float deg = s_deg;
    const int   mp  = (m + 31) & ~31;   // pad to 32 (4-group stagger granularity)

    if (av != 0.f) {
        int pos = wcnt[w] + __popc(mask & ((1u << l) - 1u));
        jlist[pos] = t;
        cav[pos]   = av;
    }
    if (t >= m && t < mp) { jlist[t] = 0; cav[t] = 0.f; }
    __syncthreads();

    // stage compacted, transposed edge slice into the bank-padded layout
    if (t < mp) {
        const int idx = ((t >> 5) * 36) + (t & 31);
        if (t < m) {
            const int j = jlist[t];
            const float4* e4 = (const float4*)(ef + ((size_t)row * 256 + j) * 16);
            float4 v0 = e4[0], v1 = e4[1], v2 = e4[2], v3 = e4[3];
            eTp[0][idx]  = v0.x; eTp[1][idx]  = v0.y; eTp[2][idx]  = v0.z; eTp[3][idx]  = v0.w;
            eTp[4][idx]  = v1.x; eTp[5][idx]  = v1.y; eTp[6][idx]  = v1.z; eTp[7][idx]  = v1.w;
            eTp[8][idx]  = v2.x; eTp[9][idx]  = v2.y; eTp[10][idx] = v2.z; eTp[11][idx] = v2.w;
            eTp[12][idx] = v3.x; eTp[13][idx] = v3.y; eTp[14][idx] = v3.z; eTp[15][idx] = v3.w;
        } else {
#pragma unroll
            for (int k = 0; k < 16; k++) eTp[k][idx] = 0.f;
        }
    }
    __syncthreads();

    const int nch  = mp >> 3;                       // 8-j chunks (multiple of 4)
    const int goff = (l >> 3) * (nch >> 2);         // lane-group chunk rotation

    u64 S0 = 0ull, S1 = 0ull;
#pragma unroll 1
    for (int i = 0; i < nch; i++) {
        int c = i + goff; if (c >= nch) c -= nch;
        const int j8 = c << 3;
        const int eb = ((j8 >> 5) * 36) + (j8 & 31);

        const int4 jla = *(const int4*)&jlist[j8];
        const int4 jlb = *(const int4*)&jlist[j8 + 4];
        const float b0 = BvF[(size_t)jla.x * 256 + t];
        const float b1 = BvF[(size_t)jla.y * 256 + t];
        const float b2 = BvF[(size_t)jla.z * 256 + t];
        const float b3 = BvF[(size_t)jla.w * 256 + t];
        const float b4 = BvF[(size_t)jlb.x * 256 + t];
        const float b5 = BvF[(size_t)jlb.y * 256 + t];
        const float b6 = BvF[(size_t)jlb.z * 256 + t];
        const float b7 = BvF[(size_t)jlb.w * 256 + t];

        // ---- phase A: j8..j8+3 ----
        {
            u64 acc0 = a2, acc1 = a2, acc0b = 0ull, acc1b = 0ull;
#pragma unroll
            for (int k = 0; k < 16; k += 2) {
                ull2 e0 = *(const ull2*)&eTp[k][eb];
                ull2 e1 = *(const ull2*)&eTp[k + 1][eb];
                acc0  = fma2(e0.x, wd[k],     acc0);
                acc1  = fma2(e0.y, wd[k],     acc1);
                acc0b = fma2(e1.x, wd[k + 1], acc0b);
                acc1b = fma2(e1.y, wd[k + 1], acc1b);
            }
            acc0 = add2(acc0, acc0b);
            acc1 = add2(acc1, acc1b);
            const ull2 cp = *(const ull2*)&cav[j8];
            S0 = fma2(cp.x, max2z(add2(acc0, pack2(b0, b1))), S0);
            S1 = fma2(cp.y, max2z(add2(acc1, pack2(b2, b3))), S1);
        }
        // ---- phase B: j8+4..j8+7 ----
        {
            u64 acc0 = a2, acc1 = a2, acc0b = 0ull, acc1b = 0ull;
#pragma unroll
            for (int k = 0; k < 16; k += 2) {
                ull2 e0 = *(const ull2*)&eTp[k][eb + 4];
                ull2 e1 = *(const ull2*)&eTp[k + 1][eb + 4];
                acc0  = fma2(e0.x, wd[k],     acc0);
                acc1  = fma2(e0.y, wd[k],     acc1);
                acc0b = fma2(e1.x, wd[k + 1], acc0b);
                acc1b = fma2(e1.y, wd[k + 1], acc1b);
            }
            acc0 = add2(acc0, acc0b);
            acc1 = add2(acc1, acc1b);
            const ull2 cp = *(const ull2*)&cav[j8 + 4];
            S0 = fma2(cp.x, max2z(add2(acc0, pack2(b4, b5))), S0);
            S1 = fma2(cp.y, max2z(add2(acc1, pack2(b6, b7))), S1);
        }
    }

    const float2 s0 = unpack2(S0), s1 = unpack2(S1);
    g_S[(size_t)row * 256 + t] = (s0.x + s0.y) + (s1.x + s1.y);
    if (t == 0) g_deg[row] = deg;
}

// ---------------------------------------------------------------------------
// Update v4: row-pair-packed operands. (Unchanged.)
// ---------------------------------------------------------------------------
__global__ __launch_bounds__(256) void update_kernel(
    const float* __restrict__ h,  const float* __restrict__ W2,
    const float* __restrict__ b2, const float* __restrict__ U1,
    const float* __restrict__ c1, const float* __restrict__ U2,
    const float* __restrict__ c2, float* __restrict__ out)
{
    __shared__ __align__(16) u64 Stp[256][4];
    __shared__ __align__(16) u64 xdp[256][4];
    __shared__ u64 red[1728];
    __shared__ u64 degp[4];

    const int t  = threadIdx.x;
    const int r0 = blockIdx.x * 8;

    {
        const float* Sb = g_S + (size_t)r0 * 256;
#pragma unroll
        for (int rp = 0; rp < 4; rp++)
            Stp[t][rp] = pack2(Sb[(size_t)(2 * rp) * 256 + t],
                               Sb[(size_t)(2 * rp + 1) * 256 + t]);
        if (t < 128) {
            const float* hb = h + (size_t)r0 * 128;
#pragma unroll
            for (int rp = 0; rp < 4; rp++)
                xdp[t][rp] = pack2(hb[(size_t)(2 * rp) * 128 + t],
                                   hb[(size_t)(2 * rp + 1) * 128 + t]);
        }
        if (t < 4) degp[t] = pack2(g_deg[r0 + 2 * t], g_deg[r0 + 2 * t + 1]);
    }
    __syncthreads();

    // stage 1: agg = S @ W2 + deg*b2
    {
        const int cp = t & 63, kq = t >> 6, k0 = kq * 64;
        const u64* Wb = (const u64*)W2 + cp;
        u64 acc[4][2] = {{0ull,0ull},{0ull,0ull},{0ull,0ull},{0ull,0ull}};
#pragma unroll 1
        for (int kk = 0; kk < 64; kk += 8) {
            u64 wv[8];
#pragma unroll
            for (int i = 0; i < 8; i++)
                wv[i] = Wb[(size_t)(k0 + kk + i) * 64];
#pragma unroll
            for (int i = 0; i < 8; i++) {
                float2 wf = unpack2(wv[i]);
                u64 w0 = dup2(wf.x), w1 = dup2(wf.y);
                const int k = k0 + kk + i;
                ull2 s01 = *(const ull2*)&Stp[k][0];
                ull2 s23 = *(const ull2*)&Stp[k][2];
                acc[0][0] = fma2(s01.x, w0, acc[0][0]); acc[0][1] = fma2(s01.x, w1, acc[0][1]);
                acc[1][0] = fma2(s01.y, w0, acc[1][0]); acc[1][1] = fma2(s01.y, w1, acc[1][1]);
                acc[2][0] = fma2(s23.x, w0, acc[2][0]); acc[2][1] = fma2(s23.x, w1, acc[2][1]);
                acc[3][0] = fma2(s23.y, w0, acc[3][0]); acc[3][1] = fma2(s23.y, w1, acc[3][1]);
            }
        }
        if (kq > 0) {
#pragma unroll
            for (int rp = 0; rp < 4; rp++) {
                red[((kq - 1) * 64 + cp) * 9 + 2 * rp]     = acc[rp][0];
                red[((kq - 1) * 64 + cp) * 9 + 2 * rp + 1] = acc[rp][1];
            }
        }
        __syncthreads();
        if (kq == 0) {
            float2 bf = unpack2(((const u64*)b2)[cp]);
            u64 bd0 = dup2(bf.x), bd1 = dup2(bf.y);
#pragma unroll
            for (int rp = 0; rp < 4; rp++) {
                u64 s0 = add2(add2(acc[rp][0], red[cp * 9 + 2 * rp]),
                              add2(red[(64 + cp) * 9 + 2 * rp], red[(128 + cp) * 9 + 2 * rp]));
                u64 s1 = add2(add2(acc[rp][1], red[cp * 9 + 2 * rp + 1]),
                              add2(red[(64 + cp) * 9 + 2 * rp + 1], red[(128 + cp) * 9 + 2 * rp + 1]));
                xdp[128 + 2 * cp][rp]     = fma2(degp[rp], bd0, s0);
                xdp[128 + 2 * cp + 1][rp] = fma2(degp[rp], bd1, s1);
            }
        }
    }
    __syncthreads();

    // stage 2: uh = relu(x @ U1 + c1)
    {
        const int cp = t & 127, kh = t >> 7, k0 = kh * 128;
        const u64* Wb = (const u64*)U1 + cp;
        u64 acc[4][2] = {{0ull,0ull},{0ull,0ull},{0ull,0ull},{0ull,0ull}};
#pragma unroll 1
        for (int kk = 0; kk < 128; kk += 8) {
            u64 wv[8];
#pragma unroll
            for (int i = 0; i < 8; i++)
                wv[i] = Wb[(size_t)(k0 + kk + i) * 128];
#pragma unroll
            for (int i = 0; i < 8; i++) {
                float2 wf = unpack2(wv[i]);
                u64 w0 = dup2(wf.x), w1 = dup2(wf.y);
                const int k = k0 + kk + i;
                ull2 x01 = *(const ull2*)&xdp[k][0];
                ull2 x23 = *(const ull2*)&xdp[k][2];
                acc[0][0] = fma2(x01.x, w0, acc[0][0]); acc[0][1] = fma2(x01.x, w1, acc[0][1]);
                acc[1][0] = fma2(x01.y, w0, acc[1][0]); acc[1][1] = fma2(x01.y, w1, acc[1][1]);
                acc[2][0] = fma2(x23.x, w0, acc[2][0]); acc[2][1] = fma2(x23.x, w1, acc[2][1]);
                acc[3][0] = fma2(x23.y, w0, acc[3][0]); acc[3][1] = fma2(x23.y, w1, acc[3][1]);
            }
        }
        if (kh == 1) {
#pragma unroll
            for (int rp = 0; rp < 4; rp++) {
                red[cp * 9 + 2 * rp]     = acc[rp][0];
                red[cp * 9 + 2 * rp + 1] = acc[rp][1];
            }
        }
        __syncthreads();
        if (kh == 0) {
            float2 cf = unpack2(((const u64*)c1)[cp]);
            u64 c0 = dup2(cf.x), c1d = dup2(cf.y);
#pragma unroll
            for (int rp = 0; rp < 4; rp++) {
                Stp[2 * cp][rp]     = max2z(add2(add2(acc[rp][0], red[cp * 9 + 2 * rp]), c0));
                Stp[2 * cp + 1][rp] = max2z(add2(add2(acc[rp][1], red[cp * 9 + 2 * rp + 1]), c1d));
            }
        }
    }
    __syncthreads();

    // stage 3: out = uh @ U2 + c2
    {
        const int cp = t & 63, kq = t >> 6, k0 = kq * 64;
        const u64* Wb = (const u64*)U2 + cp;
        u64 acc[4][2] = {{0ull,0ull},{0ull,0ull},{0ull,0ull},{0ull,0ull}};
#pragma unroll 1
        for (int kk = 0; kk < 64; kk += 8) {
            u64 wv[8];
#pragma unroll
            for (int i = 0; i < 8; i++)
                wv[i] = Wb[(size_t)(k0 + kk + i) * 64];
#pragma unroll
            for (int i = 0; i < 8; i++) {
                float2 wf = unpack2(wv[i]);
                u64 w0 = dup2(wf.x), w1 = dup2(wf.y);
                const int k = k0 + kk + i;
                ull2 u01 = *(const ull2*)&Stp[k][0];
                ull2 u23 = *(const ull2*)&Stp[k][2];
                acc[0][0] = fma2(u01.x, w0, acc[0][0]); acc[0][1] = fma2(u01.x, w1, acc[0][1]);
                acc[1][0] = fma2(u01.y, w0, acc[1][0]); acc[1][1] = fma2(u01.y, w1, acc[1][1]);
                acc[2][0] = fma2(u23.x, w0, acc[2][0]); acc[2][1] = fma2(u23.x, w1, acc[2][1]);
                acc[3][0] = fma2(u23.y, w0, acc[3][0]); acc[3][1] = fma2(u23.y, w1, acc[3][1]);
            }
        }
        if (kq > 0) {
#pragma unroll
            for (int rp = 0; rp < 4; rp++) {
                red[((kq - 1) * 64 + cp) * 9 + 2 * rp]     = acc[rp][0];
                red[((kq - 1) * 64 + cp) * 9 + 2 * rp + 1] = acc[rp][1];
            }
        }
        __syncthreads();
        if (kq == 0) {
            const u64 c2p = ((const u64*)c2)[cp];
#pragma unroll
            for (int rp = 0; rp < 4; rp++) {
                u64 s0 = add2(add2(acc[rp][0], red[cp * 9 + 2 * rp]),
                              add2(red[(64 + cp) * 9 + 2 * rp], red[(128 + cp) * 9 + 2 * rp]));
                u64 s1 = add2(add2(acc[rp][1], red[cp * 9 + 2 * rp + 1]),
                              add2(red[(64 + cp) * 9 + 2 * rp + 1], red[(128 + cp) * 9 + 2 * rp + 1]));
                float2 f0 = unpack2(s0), f1 = unpack2(s1);
                ((u64*)out)[(size_t)(r0 + 2 * rp) * 64 + cp]     = add2(pack2(f0.x, f1.x), c2p);
                ((u64*)out)[(size_t)(r0 + 2 * rp + 1) * 64 + cp] = add2(pack2(f0.y, f1.y), c2p);
            }
        }
    }
}

extern "C" void kernel_launch(void* const* d_in, const int* in_sizes, int n_in,
                              void* d_out, int out_size)
{
    const float* h   = (const float*)d_in[0];
    const float* adj = (const float*)d_in[1];
    const float* ef  = (const float*)d_in[2];
    const float* W1  = (const float*)d_in[3];
    const float* b1  = (const float*)d_in[4];
    const float* W2  = (const float*)d_in[5];
    const float* b2  = (const float*)d_in[6];
    const float* U1  = (const float*)d_in[7];
    const float* c1  = (const float*)d_in[8];
    const float* U2  = (const float*)d_in[9];
    const float* c2  = (const float*)d_in[10];

    const int rows = in_sizes[0] / 128;   // B*N = 2048

    align_kernel<<<1, 32>>>();            // capture slot #4 = mpnn_main
    align_kernel2<<<1, 32>>>();
    precompute_kernel<<<rows / 8, 256>>>(h, W1, b1);
    mpnn_main<<<rows, 256>>>(adj, ef, W1);
    update_kernel<<<rows / 8, 256>>>(h, W2, b2, U1, c1, U2, c2, (float*)d_out);
}